// round 2
// baseline (speedup 1.0000x reference)
#include <cuda_runtime.h>
#include <cuda_bf16.h>
#include <math.h>

// Problem constants
#define BATCH 2
#define SEQ   1024
#define HID   2048
#define NH    32
#define NKV   4
#define GRP   8            // NH / NKV
#define HD    128
#define NQKV  5120         // (NH + 2*NKV) * HD
#define TOK   (BATCH*SEQ)  // 2048
#define SCALE 0.08838834764831845f
#define RMS_EPS 1e-6f

// -------------------- scratch (static device globals; no allocation) -------
__device__ float g_qkv[TOK * NQKV];                 // 40 MB
__device__ float g_q[BATCH * NH * SEQ * HD];        // 32 MB
__device__ float g_k[BATCH * NKV * SEQ * HD];       // 4 MB
__device__ float g_v[BATCH * NKV * SEQ * HD];       // 4 MB
__device__ float g_ctx[TOK * NH * HD];              // 32 MB

// ---------------------------------------------------------------------------
// SGEMM: C[M,N] = A[M,K] @ B[K,N], row-major, all dims multiples of 128/8.
// 128x128 block tile, BK=8, 256 threads, 8x8 per-thread micro tile.
// ---------------------------------------------------------------------------
__global__ __launch_bounds__(256) void sgemm128(
    const float* __restrict__ A, const float* __restrict__ Bm,
    float* __restrict__ C, int M, int N, int Kdim)
{
    __shared__ float As[8][128];
    __shared__ float Bs[8][128];

    const int bm = blockIdx.y, bn = blockIdx.x;
    const int tid = threadIdx.x;
    const int tr = tid >> 4, tc = tid & 15;

    const int arow = tid >> 1, acol = (tid & 1) * 4;
    const int brow = tid >> 5, bcol = (tid & 31) * 4;

    const float* Ab = A + (size_t)(bm * 128) * Kdim;
    const float* Bb = Bm + bn * 128;

    float acc[8][8];
#pragma unroll
    for (int i = 0; i < 8; i++)
#pragma unroll
        for (int j = 0; j < 8; j++) acc[i][j] = 0.f;

    for (int k0 = 0; k0 < Kdim; k0 += 8) {
        float4 a4 = *(const float4*)(Ab + (size_t)arow * Kdim + k0 + acol);
        As[acol + 0][arow] = a4.x;
        As[acol + 1][arow] = a4.y;
        As[acol + 2][arow] = a4.z;
        As[acol + 3][arow] = a4.w;
        float4 b4 = *(const float4*)(Bb + (size_t)(k0 + brow) * N + bcol);
        *(float4*)(&Bs[brow][bcol]) = b4;
        __syncthreads();

#pragma unroll
        for (int kk = 0; kk < 8; kk++) {
            float ra[8], rb[8];
            *(float4*)(ra)     = *(const float4*)(&As[kk][tr * 8]);
            *(float4*)(ra + 4) = *(const float4*)(&As[kk][tr * 8 + 4]);
            *(float4*)(rb)     = *(const float4*)(&Bs[kk][tc * 8]);
            *(float4*)(rb + 4) = *(const float4*)(&Bs[kk][tc * 8 + 4]);
#pragma unroll
            for (int i = 0; i < 8; i++)
#pragma unroll
                for (int j = 0; j < 8; j++)
                    acc[i][j] = fmaf(ra[i], rb[j], acc[i][j]);
        }
        __syncthreads();
    }

    float* Cb = C + (size_t)(bm * 128 + tr * 8) * N + bn * 128 + tc * 8;
#pragma unroll
    for (int i = 0; i < 8; i++) {
        *(float4*)(Cb + (size_t)i * N)     = make_float4(acc[i][0], acc[i][1], acc[i][2], acc[i][3]);
        *(float4*)(Cb + (size_t)i * N + 4) = make_float4(acc[i][4], acc[i][5], acc[i][6], acc[i][7]);
    }
}

// ---------------------------------------------------------------------------
// Per-head RMSNorm + RoPE split of qkv into Q [B,NH,S,D], K/V [B,NKV,S,D]
// grid: (TOK, 40), block: 128 threads (one per d)
// slots: 0..31 q heads, 32..35 k heads, 36..39 v heads (copy only)
// ---------------------------------------------------------------------------
__global__ __launch_bounds__(128) void norm_rope_kernel(
    const float* __restrict__ qkv, const float* __restrict__ cosb,
    const float* __restrict__ sinb, const float* __restrict__ qw,
    const float* __restrict__ kw,
    float* __restrict__ Q, float* __restrict__ K, float* __restrict__ V)
{
    const int token = blockIdx.x;
    const int slot  = blockIdx.y;
    const int d     = threadIdx.x;
    const int b = token / SEQ, s = token % SEQ;

    const float x = qkv[(size_t)token * NQKV + slot * HD + d];

    if (slot >= 36) {  // V: straight copy
        const int kh = slot - 36;
        V[((size_t)(b * NKV + kh) * SEQ + s) * HD + d] = x;
        return;
    }

    __shared__ float xn[HD];
    __shared__ float red[4];

    float ss = x * x;
#pragma unroll
    for (int o = 16; o > 0; o >>= 1) ss += __shfl_xor_sync(0xffffffffu, ss, o);
    if ((d & 31) == 0) red[d >> 5] = ss;
    __syncthreads();
    const float tot = red[0] + red[1] + red[2] + red[3];
    const float inv = rsqrtf(tot * (1.0f / HD) + RMS_EPS);

    const float* w = (slot < 32) ? qw : kw;
    const float v = x * inv * w[d];
    xn[d] = v;
    __syncthreads();

    const float rot = (d < 64) ? -xn[d + 64] : xn[d - 64];
    const float c  = cosb[(size_t)s * HD + d];
    const float sn = sinb[(size_t)s * HD + d];
    const float out = v * c + rot * sn;

    if (slot < 32)
        Q[((size_t)(b * NH + slot) * SEQ + s) * HD + d] = out;
    else
        K[((size_t)(b * NKV + (slot - 32)) * SEQ + s) * HD + d] = out;
}

// ---------------------------------------------------------------------------
// Causal GQA flash attention.
// grid: (SEQ/64, NH, BATCH), block 256.
// 64 queries per block, iterate 64-key tiles with online softmax.
// ctx written as [B, S, NH*HD] (head-major within the row) for the O GEMM.
// ---------------------------------------------------------------------------
#define QS_STRIDE 129
#define SS_STRIDE 65
__global__ __launch_bounds__(256) void attn_kernel(
    const float* __restrict__ Q, const float* __restrict__ K,
    const float* __restrict__ V, float* __restrict__ ctx)
{
    extern __shared__ float sm[];
    float* Qs  = sm;                       // 64*129
    float* Ks  = Qs + 64 * QS_STRIDE;      // 64*129
    float* Vs  = Ks + 64 * QS_STRIDE;      // 64*128
    float* Ss  = Vs + 64 * 128;            // 64*65
    float* m_s = Ss + 64 * SS_STRIDE;      // 64
    float* l_s = m_s + 64;                 // 64
    float* sc_s = l_s + 64;                // 64

    const int m_tile = blockIdx.x;
    const int h = blockIdx.y;
    const int b = blockIdx.z;
    const int kh = h / GRP;
    const int tid = threadIdx.x;
    const int m0 = m_tile * 64;

    const float* Qbase = Q + ((size_t)(b * NH + h) * SEQ + m0) * HD;
    const float* Kbase = K + ((size_t)(b * NKV + kh) * SEQ) * HD;
    const float* Vbase = V + ((size_t)(b * NKV + kh) * SEQ) * HD;

    // load Q tile (64 x 128)
    for (int i = tid; i < 64 * 32; i += 256) {
        int r = i >> 5, c4 = (i & 31) * 4;
        float4 q4 = *(const float4*)(Qbase + (size_t)r * HD + c4);
        Qs[r * QS_STRIDE + c4 + 0] = q4.x;
        Qs[r * QS_STRIDE + c4 + 1] = q4.y;
        Qs[r * QS_STRIDE + c4 + 2] = q4.z;
        Qs[r * QS_STRIDE + c4 + 3] = q4.w;
    }
    if (tid < 64) { m_s[tid] = -1e30f; l_s[tid] = 0.f; }

    const int tr = tid >> 4, tc = tid & 15;
    const int r0 = tr * 4;       // rows for both score and output tiles
    const int cS0 = tc * 4;      // score columns (4)
    const int cO0 = tc * 8;      // output columns (8)

    float acc[4][8];
#pragma unroll
    for (int i = 0; i < 4; i++)
#pragma unroll
        for (int j = 0; j < 8; j++) acc[i][j] = 0.f;

    __syncthreads();

    const int ntiles = m_tile + 1;
    for (int t = 0; t < ntiles; ++t) {
        const int n0 = t * 64;
        // load K, V tiles
        for (int i = tid; i < 64 * 32; i += 256) {
            int r = i >> 5, c4 = (i & 31) * 4;
            float4 k4 = *(const float4*)(Kbase + (size_t)(n0 + r) * HD + c4);
            Ks[r * QS_STRIDE + c4 + 0] = k4.x;
            Ks[r * QS_STRIDE + c4 + 1] = k4.y;
            Ks[r * QS_STRIDE + c4 + 2] = k4.z;
            Ks[r * QS_STRIDE + c4 + 3] = k4.w;
            float4 v4 = *(const float4*)(Vbase + (size_t)(n0 + r) * HD + c4);
            *(float4*)(Vs + r * 128 + c4) = v4;
        }
        __syncthreads();

        // scores: 4x4 per thread over 64x64 tile
        float s[4][4];
#pragma unroll
        for (int i = 0; i < 4; i++)
#pragma unroll
            for (int j = 0; j < 4; j++) s[i][j] = 0.f;

        for (int d = 0; d < HD; ++d) {
            float qa[4], kb[4];
#pragma unroll
            for (int i = 0; i < 4; i++) qa[i] = Qs[(r0 + i) * QS_STRIDE + d];
#pragma unroll
            for (int j = 0; j < 4; j++) kb[j] = Ks[(cS0 + j) * QS_STRIDE + d];
#pragma unroll
            for (int i = 0; i < 4; i++)
#pragma unroll
                for (int j = 0; j < 4; j++)
                    s[i][j] = fmaf(qa[i], kb[j], s[i][j]);
        }
#pragma unroll
        for (int i = 0; i < 4; i++) {
            const int qi = m0 + r0 + i;
#pragma unroll
            for (int j = 0; j < 4; j++) {
                const int ki = n0 + cS0 + j;
                Ss[(r0 + i) * SS_STRIDE + cS0 + j] =
                    (ki <= qi) ? s[i][j] * SCALE : -1e30f;
            }
        }
        __syncthreads();

        // online softmax per row (64 rows by threads 0..63)
        if (tid < 64) {
            const int r = tid;
            const float mo = m_s[r];
            float mx = mo;
            for (int c = 0; c < 64; c++) mx = fmaxf(mx, Ss[r * SS_STRIDE + c]);
            const float scl = __expf(mo - mx);
            float l = l_s[r] * scl;
            for (int c = 0; c < 64; c++) {
                const float p = __expf(Ss[r * SS_STRIDE + c] - mx);
                Ss[r * SS_STRIDE + c] = p;
                l += p;
            }
            m_s[r] = mx; l_s[r] = l; sc_s[r] = scl;
        }
        __syncthreads();

        // rescale acc, then acc += P @ V
#pragma unroll
        for (int i = 0; i < 4; i++) {
            const float scl = sc_s[r0 + i];
#pragma unroll
            for (int j = 0; j < 8; j++) acc[i][j] *= scl;
        }
        for (int n = 0; n < 64; ++n) {
            float p[4];
#pragma unroll
            for (int i = 0; i < 4; i++) p[i] = Ss[(r0 + i) * SS_STRIDE + n];
            const float4 v0 = *(const float4*)(Vs + n * 128 + cO0);
            const float4 v1 = *(const float4*)(Vs + n * 128 + cO0 + 4);
#pragma unroll
            for (int i = 0; i < 4; i++) {
                acc[i][0] = fmaf(p[i], v0.x, acc[i][0]);
                acc[i][1] = fmaf(p[i], v0.y, acc[i][1]);
                acc[i][2] = fmaf(p[i], v0.z, acc[i][2]);
                acc[i][3] = fmaf(p[i], v0.w, acc[i][3]);
                acc[i][4] = fmaf(p[i], v1.x, acc[i][4]);
                acc[i][5] = fmaf(p[i], v1.y, acc[i][5]);
                acc[i][6] = fmaf(p[i], v1.z, acc[i][6]);
                acc[i][7] = fmaf(p[i], v1.w, acc[i][7]);
            }
        }
        __syncthreads();
    }

    // final write: ctx[b, s, h*HD + d]
#pragma unroll
    for (int i = 0; i < 4; i++) {
        const float invl = 1.0f / l_s[r0 + i];
        const int srow = m0 + r0 + i;
        float* o = g_ctx + ((size_t)b * SEQ + srow) * (NH * HD) + h * HD + cO0;
        *(float4*)(o)     = make_float4(acc[i][0] * invl, acc[i][1] * invl,
                                        acc[i][2] * invl, acc[i][3] * invl);
        *(float4*)(o + 4) = make_float4(acc[i][4] * invl, acc[i][5] * invl,
                                        acc[i][6] * invl, acc[i][7] * invl);
    }
    (void)ctx;
}

// ---------------------------------------------------------------------------
extern "C" void kernel_launch(void* const* d_in, const int* in_sizes, int n_in,
                              void* d_out, int out_size)
{
    const float* hidden = (const float*)d_in[0];   // [B,S,HID]
    const float* cosb   = (const float*)d_in[1];   // [1,S,1,D]
    const float* sinb   = (const float*)d_in[2];   // [1,S,1,D]
    const float* w_qkv  = (const float*)d_in[3];   // [HID, NQKV]
    const float* q_w    = (const float*)d_in[4];   // [D]
    const float* k_w    = (const float*)d_in[5];   // [D]
    const float* w_o    = (const float*)d_in[6];   // [NH*HD, HID]
    float* out = (float*)d_out;                    // [B,S,HID]

    float *qkv_p, *q_p, *k_p, *v_p, *ctx_p;
    cudaGetSymbolAddress((void**)&qkv_p, g_qkv);
    cudaGetSymbolAddress((void**)&q_p,   g_q);
    cudaGetSymbolAddress((void**)&k_p,   g_k);
    cudaGetSymbolAddress((void**)&v_p,   g_v);
    cudaGetSymbolAddress((void**)&ctx_p, g_ctx);

    // attention dynamic smem: (64*129*2 + 64*128 + 64*65 + 192) floats
    const int attn_smem = (64 * QS_STRIDE * 2 + 64 * 128 + 64 * SS_STRIDE + 192) * 4;
    cudaFuncSetAttribute(attn_kernel, cudaFuncAttributeMaxDynamicSharedMemorySize, attn_smem);

    // 1) QKV projection: [2048,2048] @ [2048,5120]
    sgemm128<<<dim3(NQKV / 128, TOK / 128), 256>>>(hidden, w_qkv, qkv_p, TOK, NQKV, HID);

    // 2) RMSNorm + RoPE + split
    norm_rope_kernel<<<dim3(TOK, 40), 128>>>(qkv_p, cosb, sinb, q_w, k_w, q_p, k_p, v_p);

    // 3) causal GQA attention
    attn_kernel<<<dim3(SEQ / 64, NH, BATCH), 256, attn_smem>>>(q_p, k_p, v_p, ctx_p);

    // 4) output projection: [2048,4096] @ [4096,2048]
    sgemm128<<<dim3(HID / 128, TOK / 128), 256>>>(ctx_p, w_o, out, TOK, HID, NH * HD);

    (void)in_sizes; (void)n_in; (void)out_size;
}

// round 3
// speedup vs baseline: 1.7427x; 1.7427x over previous
#include <cuda_runtime.h>
#include <cuda_bf16.h>
#include <math.h>

// Problem constants
#define BATCH 2
#define SEQ   1024
#define HID   2048
#define NH    32
#define NKV   4
#define GRP   8
#define HD    128
#define NQKV  5120
#define TOK   (BATCH*SEQ)
#define SCALE 0.08838834764831845f
#define RMS_EPS 1e-6f

// -------------------- scratch -------------------------------------------
__device__ float g_qkv[TOK * NQKV];
__device__ float g_q[BATCH * NH * SEQ * HD];
__device__ float g_k[BATCH * NKV * SEQ * HD];
__device__ float g_v[BATCH * NKV * SEQ * HD];
__device__ float g_ctx[TOK * NH * HD];

// ---------------------------------------------------------------------------
// TF32 tensor-core GEMM: C[M,N] = A[M,K] @ B[K,N], row-major.
// 128x128 tile, BK=32, 256 threads (8 warps), warp tile 32x64 via m16n8k8.
// A smem m-major [128][36] (pad for conflict-free frag loads),
// B smem k-major [32][136]. TF32 conversion at STS time (RNA rounding).
// ---------------------------------------------------------------------------
__device__ __forceinline__ unsigned f2tf32(float x) {
    unsigned y;
    asm("cvt.rna.tf32.f32 %0, %1;" : "=r"(y) : "f"(x));
    return y;
}

__global__ __launch_bounds__(256) void gemm_tf32(
    const float* __restrict__ A, const float* __restrict__ B,
    float* __restrict__ C, int M, int N, int K)
{
    __shared__ unsigned As[128][36];
    __shared__ unsigned Bs[32][136];

    const int tid  = threadIdx.x;
    const int lane = tid & 31;
    const int wid  = tid >> 5;
    const int bm = blockIdx.y, bn = blockIdx.x;

    const int wm = (wid & 3) * 32;   // warp row offset in tile
    const int wn = (wid >> 2) * 64;  // warp col offset in tile

    // global load indices
    const int arow = tid >> 1,  acol = (tid & 1) * 16;   // A: 128x32, 16 floats/thread
    const int brow = tid >> 3,  bcol = (tid & 7) * 16;   // B: 32x128, 16 floats/thread

    const float* Ag = A + (size_t)(bm * 128 + arow) * K + acol;
    const float* Bg = B + (size_t)brow * N + bn * 128 + bcol;

    const int qr = lane >> 2;   // 0..7
    const int ql = lane & 3;    // 0..3

    float acc[2][8][4];
#pragma unroll
    for (int i = 0; i < 2; i++)
#pragma unroll
        for (int j = 0; j < 8; j++)
#pragma unroll
            for (int c = 0; c < 4; c++) acc[i][j][c] = 0.f;

    for (int k0 = 0; k0 < K; k0 += 32) {
        // stage global -> regs
        float4 av[4], bv[4];
#pragma unroll
        for (int u = 0; u < 4; u++) {
            av[u] = *(const float4*)(Ag + k0 + u * 4);
            bv[u] = *(const float4*)(Bg + (size_t)k0 * N + u * 4);
        }
        __syncthreads();   // previous compute done
        // cvt + store
#pragma unroll
        for (int u = 0; u < 4; u++) {
            As[arow][acol + u * 4 + 0] = f2tf32(av[u].x);
            As[arow][acol + u * 4 + 1] = f2tf32(av[u].y);
            As[arow][acol + u * 4 + 2] = f2tf32(av[u].z);
            As[arow][acol + u * 4 + 3] = f2tf32(av[u].w);
            Bs[brow][bcol + u * 4 + 0] = f2tf32(bv[u].x);
            Bs[brow][bcol + u * 4 + 1] = f2tf32(bv[u].y);
            Bs[brow][bcol + u * 4 + 2] = f2tf32(bv[u].z);
            Bs[brow][bcol + u * 4 + 3] = f2tf32(bv[u].w);
        }
        __syncthreads();

#pragma unroll
        for (int kk = 0; kk < 4; kk++) {
            const int kb = kk * 8 + ql;
            unsigned a[2][4];
#pragma unroll
            for (int i = 0; i < 2; i++) {
                const int r = wm + i * 16 + qr;
                a[i][0] = As[r    ][kb    ];
                a[i][1] = As[r + 8][kb    ];
                a[i][2] = As[r    ][kb + 4];
                a[i][3] = As[r + 8][kb + 4];
            }
#pragma unroll
            for (int j = 0; j < 8; j++) {
                const int n = wn + j * 8 + qr;
                unsigned b0 = Bs[kb    ][n];
                unsigned b1 = Bs[kb + 4][n];
#pragma unroll
                for (int i = 0; i < 2; i++) {
                    asm volatile(
                        "mma.sync.aligned.m16n8k8.row.col.f32.tf32.tf32.f32 "
                        "{%0,%1,%2,%3}, {%4,%5,%6,%7}, {%8,%9}, {%0,%1,%2,%3};"
                        : "+f"(acc[i][j][0]), "+f"(acc[i][j][1]),
                          "+f"(acc[i][j][2]), "+f"(acc[i][j][3])
                        : "r"(a[i][0]), "r"(a[i][1]), "r"(a[i][2]), "r"(a[i][3]),
                          "r"(b0), "r"(b1));
                }
            }
        }
    }

    // epilogue
#pragma unroll
    for (int i = 0; i < 2; i++) {
        const int r0 = bm * 128 + wm + i * 16 + qr;
#pragma unroll
        for (int j = 0; j < 8; j++) {
            const int c = bn * 128 + wn + j * 8 + ql * 2;
            *(float2*)(C + (size_t)r0 * N + c)       = make_float2(acc[i][j][0], acc[i][j][1]);
            *(float2*)(C + (size_t)(r0 + 8) * N + c) = make_float2(acc[i][j][2], acc[i][j][3]);
        }
    }
}

// ---------------------------------------------------------------------------
// RMSNorm + RoPE + split
// ---------------------------------------------------------------------------
__global__ __launch_bounds__(128) void norm_rope_kernel(
    const float* __restrict__ qkv, const float* __restrict__ cosb,
    const float* __restrict__ sinb, const float* __restrict__ qw,
    const float* __restrict__ kw,
    float* __restrict__ Q, float* __restrict__ K, float* __restrict__ V)
{
    const int token = blockIdx.x;
    const int slot  = blockIdx.y;
    const int d     = threadIdx.x;
    const int b = token / SEQ, s = token % SEQ;

    const float x = qkv[(size_t)token * NQKV + slot * HD + d];

    if (slot >= 36) {
        const int kh = slot - 36;
        V[((size_t)(b * NKV + kh) * SEQ + s) * HD + d] = x;
        return;
    }

    __shared__ float xn[HD];
    __shared__ float red[4];

    float ss = x * x;
#pragma unroll
    for (int o = 16; o > 0; o >>= 1) ss += __shfl_xor_sync(0xffffffffu, ss, o);
    if ((d & 31) == 0) red[d >> 5] = ss;
    __syncthreads();
    const float tot = red[0] + red[1] + red[2] + red[3];
    const float inv = rsqrtf(tot * (1.0f / HD) + RMS_EPS);

    const float* w = (slot < 32) ? qw : kw;
    const float v = x * inv * w[d];
    xn[d] = v;
    __syncthreads();

    const float rot = (d < 64) ? -xn[d + 64] : xn[d - 64];
    const float c  = cosb[(size_t)s * HD + d];
    const float sn = sinb[(size_t)s * HD + d];
    const float out = v * c + rot * sn;

    if (slot < 32)
        Q[((size_t)(b * NH + slot) * SEQ + s) * HD + d] = out;
    else
        K[((size_t)(b * NKV + (slot - 32)) * SEQ + s) * HD + d] = out;
}

// ---------------------------------------------------------------------------
// Causal GQA flash attention (fp32 FFMA; softmax parallelized 4 thr/row)
// ---------------------------------------------------------------------------
#define QS_STRIDE 129
#define SS_STRIDE 65
__global__ __launch_bounds__(256) void attn_kernel(
    const float* __restrict__ Q, const float* __restrict__ K,
    const float* __restrict__ V, float* __restrict__ ctx)
{
    extern __shared__ float sm[];
    float* Qs  = sm;
    float* Ks  = Qs + 64 * QS_STRIDE;
    float* Vs  = Ks + 64 * QS_STRIDE;
    float* Ss  = Vs + 64 * 128;
    float* m_s = Ss + 64 * SS_STRIDE;
    float* l_s = m_s + 64;
    float* sc_s = l_s + 64;

    const int m_tile = blockIdx.x;
    const int h = blockIdx.y;
    const int b = blockIdx.z;
    const int kh = h / GRP;
    const int tid = threadIdx.x;
    const int m0 = m_tile * 64;

    const float* Qbase = Q + ((size_t)(b * NH + h) * SEQ + m0) * HD;
    const float* Kbase = K + ((size_t)(b * NKV + kh) * SEQ) * HD;
    const float* Vbase = V + ((size_t)(b * NKV + kh) * SEQ) * HD;

    for (int i = tid; i < 64 * 32; i += 256) {
        int r = i >> 5, c4 = (i & 31) * 4;
        float4 q4 = *(const float4*)(Qbase + (size_t)r * HD + c4);
        Qs[r * QS_STRIDE + c4 + 0] = q4.x;
        Qs[r * QS_STRIDE + c4 + 1] = q4.y;
        Qs[r * QS_STRIDE + c4 + 2] = q4.z;
        Qs[r * QS_STRIDE + c4 + 3] = q4.w;
    }
    if (tid < 64) { m_s[tid] = -1e30f; l_s[tid] = 0.f; }

    const int tr = tid >> 4, tc = tid & 15;
    const int r0 = tr * 4;
    const int cS0 = tc * 4;
    const int cO0 = tc * 8;

    float acc[4][8];
#pragma unroll
    for (int i = 0; i < 4; i++)
#pragma unroll
        for (int j = 0; j < 8; j++) acc[i][j] = 0.f;

    __syncthreads();

    const int ntiles = m_tile + 1;
    for (int t = 0; t < ntiles; ++t) {
        const int n0 = t * 64;
        for (int i = tid; i < 64 * 32; i += 256) {
            int r = i >> 5, c4 = (i & 31) * 4;
            float4 k4 = *(const float4*)(Kbase + (size_t)(n0 + r) * HD + c4);
            Ks[r * QS_STRIDE + c4 + 0] = k4.x;
            Ks[r * QS_STRIDE + c4 + 1] = k4.y;
            Ks[r * QS_STRIDE + c4 + 2] = k4.z;
            Ks[r * QS_STRIDE + c4 + 3] = k4.w;
            float4 v4 = *(const float4*)(Vbase + (size_t)(n0 + r) * HD + c4);
            *(float4*)(Vs + r * 128 + c4) = v4;
        }
        __syncthreads();

        float s[4][4];
#pragma unroll
        for (int i = 0; i < 4; i++)
#pragma unroll
            for (int j = 0; j < 4; j++) s[i][j] = 0.f;

        for (int d = 0; d < HD; ++d) {
            float qa[4], kb[4];
#pragma unroll
            for (int i = 0; i < 4; i++) qa[i] = Qs[(r0 + i) * QS_STRIDE + d];
#pragma unroll
            for (int j = 0; j < 4; j++) kb[j] = Ks[(cS0 + j) * QS_STRIDE + d];
#pragma unroll
            for (int i = 0; i < 4; i++)
#pragma unroll
                for (int j = 0; j < 4; j++)
                    s[i][j] = fmaf(qa[i], kb[j], s[i][j]);
        }
#pragma unroll
        for (int i = 0; i < 4; i++) {
            const int qi = m0 + r0 + i;
#pragma unroll
            for (int j = 0; j < 4; j++) {
                const int ki = n0 + cS0 + j;
                Ss[(r0 + i) * SS_STRIDE + cS0 + j] =
                    (ki <= qi) ? s[i][j] * SCALE : -1e30f;
            }
        }
        __syncthreads();

        // online softmax: 4 threads per row, 16 cols each, quad shfl reduce
        {
            const int sr = tid >> 2;       // row 0..63
            const int sl = tid & 3;        // quad lane
            const int cb = sl * 16;
            float mx = -1e30f;
#pragma unroll
            for (int c = 0; c < 16; c++)
                mx = fmaxf(mx, Ss[sr * SS_STRIDE + cb + c]);
            mx = fmaxf(mx, __shfl_xor_sync(0xffffffffu, mx, 1));
            mx = fmaxf(mx, __shfl_xor_sync(0xffffffffu, mx, 2));
            const float mo = m_s[sr];
            mx = fmaxf(mx, mo);
            float l = 0.f;
#pragma unroll
            for (int c = 0; c < 16; c++) {
                const float p = __expf(Ss[sr * SS_STRIDE + cb + c] - mx);
                Ss[sr * SS_STRIDE + cb + c] = p;
                l += p;
            }
            l += __shfl_xor_sync(0xffffffffu, l, 1);
            l += __shfl_xor_sync(0xffffffffu, l, 2);
            if (sl == 0) {
                const float scl = __expf(mo - mx);
                l_s[sr] = l_s[sr] * scl + l;
                m_s[sr] = mx;
                sc_s[sr] = scl;
            }
        }
        __syncthreads();

#pragma unroll
        for (int i = 0; i < 4; i++) {
            const float scl = sc_s[r0 + i];
#pragma unroll
            for (int j = 0; j < 8; j++) acc[i][j] *= scl;
        }
        for (int n = 0; n < 64; ++n) {
            float p[4];
#pragma unroll
            for (int i = 0; i < 4; i++) p[i] = Ss[(r0 + i) * SS_STRIDE + n];
            const float4 v0 = *(const float4*)(Vs + n * 128 + cO0);
            const float4 v1 = *(const float4*)(Vs + n * 128 + cO0 + 4);
#pragma unroll
            for (int i = 0; i < 4; i++) {
                acc[i][0] = fmaf(p[i], v0.x, acc[i][0]);
                acc[i][1] = fmaf(p[i], v0.y, acc[i][1]);
                acc[i][2] = fmaf(p[i], v0.z, acc[i][2]);
                acc[i][3] = fmaf(p[i], v0.w, acc[i][3]);
                acc[i][4] = fmaf(p[i], v1.x, acc[i][4]);
                acc[i][5] = fmaf(p[i], v1.y, acc[i][5]);
                acc[i][6] = fmaf(p[i], v1.z, acc[i][6]);
                acc[i][7] = fmaf(p[i], v1.w, acc[i][7]);
            }
        }
        __syncthreads();
    }

#pragma unroll
    for (int i = 0; i < 4; i++) {
        const float invl = 1.0f / l_s[r0 + i];
        const int srow = m0 + r0 + i;
        float* o = g_ctx + ((size_t)b * SEQ + srow) * (NH * HD) + h * HD + cO0;
        *(float4*)(o)     = make_float4(acc[i][0] * invl, acc[i][1] * invl,
                                        acc[i][2] * invl, acc[i][3] * invl);
        *(float4*)(o + 4) = make_float4(acc[i][4] * invl, acc[i][5] * invl,
                                        acc[i][6] * invl, acc[i][7] * invl);
    }
    (void)ctx;
}

// ---------------------------------------------------------------------------
extern "C" void kernel_launch(void* const* d_in, const int* in_sizes, int n_in,
                              void* d_out, int out_size)
{
    const float* hidden = (const float*)d_in[0];
    const float* cosb   = (const float*)d_in[1];
    const float* sinb   = (const float*)d_in[2];
    const float* w_qkv  = (const float*)d_in[3];
    const float* q_w    = (const float*)d_in[4];
    const float* k_w    = (const float*)d_in[5];
    const float* w_o    = (const float*)d_in[6];
    float* out = (float*)d_out;

    float *qkv_p, *q_p, *k_p, *v_p, *ctx_p;
    cudaGetSymbolAddress((void**)&qkv_p, g_qkv);
    cudaGetSymbolAddress((void**)&q_p,   g_q);
    cudaGetSymbolAddress((void**)&k_p,   g_k);
    cudaGetSymbolAddress((void**)&v_p,   g_v);
    cudaGetSymbolAddress((void**)&ctx_p, g_ctx);

    const int attn_smem = (64 * QS_STRIDE * 2 + 64 * 128 + 64 * SS_STRIDE + 192) * 4;
    cudaFuncSetAttribute(attn_kernel, cudaFuncAttributeMaxDynamicSharedMemorySize, attn_smem);

    // 1) QKV projection (tf32 tensor cores)
    gemm_tf32<<<dim3(NQKV / 128, TOK / 128), 256>>>(hidden, w_qkv, qkv_p, TOK, NQKV, HID);

    // 2) RMSNorm + RoPE + split
    norm_rope_kernel<<<dim3(TOK, 40), 128>>>(qkv_p, cosb, sinb, q_w, k_w, q_p, k_p, v_p);

    // 3) causal GQA attention
    attn_kernel<<<dim3(SEQ / 64, NH, BATCH), 256, attn_smem>>>(q_p, k_p, v_p, ctx_p);

    // 4) output projection (tf32 tensor cores)
    gemm_tf32<<<dim3(HID / 128, TOK / 128), 256>>>(ctx_p, w_o, out, TOK, HID, NH * HD);

    (void)in_sizes; (void)n_in; (void)out_size;
}